// round 2
// baseline (speedup 1.0000x reference)
#include <cuda_runtime.h>
#include <math.h>

// Problem constants
constexpr int Bc  = 4;
constexpr int Sc  = 2048;
constexpr int Dc  = 1024;
constexpr int Hc  = 16;
constexpr int DKc = 64;
constexpr int MROWS  = Bc * Sc;      // 8192
constexpr int GROUPS = Bc * Hc;      // 64 attention groups of [2048, 64]

// Scratch (device globals: no allocation allowed)
__device__ float g_QP[MROWS * Dc];
__device__ float g_KP[MROWS * Dc];
__device__ float g_VP[MROWS * Dc];
__device__ float g_CTX[MROWS * Dc];
__device__ float g_XO[MROWS * Dc];

// ---------------------------------------------------------------------------
// GEMM: C[M,N] = A[M,K] @ W[N,K]^T + bias[N]   (torch Linear semantics)
// 128x128 block tile, BK=16, 256 threads, 8x8 per thread (split 4+4 halves)
// ---------------------------------------------------------------------------
__global__ __launch_bounds__(256) void gemm_nt_bias(
    const float* __restrict__ A, const float* __restrict__ W,
    const float* __restrict__ bias, float* __restrict__ C,
    int M, int N, int K)
{
    __shared__ float As[16][132];
    __shared__ float Ws[16][132];

    const int bm = blockIdx.y * 128;
    const int bn = blockIdx.x * 128;
    const int tid = threadIdx.x;
    const int tx = tid & 15;
    const int ty = tid >> 4;

    float acc[8][8];
#pragma unroll
    for (int i = 0; i < 8; i++)
#pragma unroll
        for (int j = 0; j < 8; j++) acc[i][j] = 0.f;

    for (int k0 = 0; k0 < K; k0 += 16) {
        // Load tiles (each thread: 2 float4 from A, 2 from W), store transposed
#pragma unroll
        for (int i = 0; i < 2; i++) {
            int idx = tid + i * 256;          // 0..511
            int row = idx >> 2;               // 0..127
            int c4  = (idx & 3) * 4;          // 0,4,8,12
            float4 av = *(const float4*)&A[(size_t)(bm + row) * K + k0 + c4];
            As[c4 + 0][row] = av.x; As[c4 + 1][row] = av.y;
            As[c4 + 2][row] = av.z; As[c4 + 3][row] = av.w;
            float4 wv = *(const float4*)&W[(size_t)(bn + row) * K + k0 + c4];
            Ws[c4 + 0][row] = wv.x; Ws[c4 + 1][row] = wv.y;
            Ws[c4 + 2][row] = wv.z; Ws[c4 + 3][row] = wv.w;
        }
        __syncthreads();

#pragma unroll
        for (int k = 0; k < 16; k++) {
            float a[8], b[8];
            *(float4*)&a[0] = *(const float4*)&As[k][ty * 4];
            *(float4*)&a[4] = *(const float4*)&As[k][64 + ty * 4];
            *(float4*)&b[0] = *(const float4*)&Ws[k][tx * 4];
            *(float4*)&b[4] = *(const float4*)&Ws[k][64 + tx * 4];
#pragma unroll
            for (int i = 0; i < 8; i++)
#pragma unroll
                for (int j = 0; j < 8; j++)
                    acc[i][j] = fmaf(a[i], b[j], acc[i][j]);
        }
        __syncthreads();
    }

    float bv[8];
    *(float4*)&bv[0] = *(const float4*)&bias[bn + tx * 4];
    *(float4*)&bv[4] = *(const float4*)&bias[bn + 64 + tx * 4];

#pragma unroll
    for (int i = 0; i < 8; i++) {
        int row = bm + ((i < 4) ? (ty * 4 + i) : (64 + ty * 4 + i - 4));
        float4 c0 = make_float4(acc[i][0] + bv[0], acc[i][1] + bv[1],
                                acc[i][2] + bv[2], acc[i][3] + bv[3]);
        float4 c1 = make_float4(acc[i][4] + bv[4], acc[i][5] + bv[5],
                                acc[i][6] + bv[6], acc[i][7] + bv[7]);
        *(float4*)&C[(size_t)row * N + bn + tx * 4]      = c0;
        *(float4*)&C[(size_t)row * N + bn + 64 + tx * 4] = c1;
    }
}

// ---------------------------------------------------------------------------
// Flash attention over [GROUPS, Sc, DKc] contiguous views.
// Block = (64 q-rows) x (full DK=64). 256 threads: (tx,ty) in 16x16,
// each thread owns a 4x4 tile of scores / output.
// Smem layouts chosen so inner loops are conflict-free float4 LDS:
//   Qs[d][q], Ks[d][kc] (d-major), Vs[k][d] (natural), Ps[k][q]
// ---------------------------------------------------------------------------
constexpr int QT = 64;
constexpr int KT = 64;
constexpr int PITCH = 68;                       // floats; 68*4B = 272B (16B aligned)
constexpr size_t FLASH_SMEM = (size_t)4 * 64 * PITCH * sizeof(float);  // 69632 B

__global__ __launch_bounds__(256) void flash_attn(
    const float* __restrict__ Q, const float* __restrict__ K,
    const float* __restrict__ V, float* __restrict__ O)
{
    extern __shared__ float sm[];
    float* Qs = sm;                   // [64][PITCH]  Qs[d][q]
    float* Ks = Qs + 64 * PITCH;      // [64][PITCH]  Ks[d][kc]
    float* Vs = Ks + 64 * PITCH;      // [64][PITCH]  Vs[k][d]
    float* Ps = Vs + 64 * PITCH;      // [64][PITCH]  Ps[k][q]

    const int g  = blockIdx.y;
    const int q0 = blockIdx.x * QT;
    const size_t base = (size_t)g * Sc * DKc;
    const int tid = threadIdx.x;
    const int tx = tid & 15;
    const int ty = tid >> 4;

    // Load Q tile transposed into Qs[d][q], folding the 1/sqrt(DK) scale.
    {
        const int r0 = (tid >> 4) * 4;     // 0..60 (q rows)
        const int dc = (tid & 15) * 4;     // 0..60 (d cols)
        const float sc = 0.125f;           // 1/sqrt(64)
#pragma unroll
        for (int r = 0; r < 4; r++) {
            float4 v4 = *(const float4*)&Q[base + (size_t)(q0 + r0 + r) * DKc + dc];
            Qs[(dc + 0) * PITCH + r0 + r] = v4.x * sc;
            Qs[(dc + 1) * PITCH + r0 + r] = v4.y * sc;
            Qs[(dc + 2) * PITCH + r0 + r] = v4.z * sc;
            Qs[(dc + 3) * PITCH + r0 + r] = v4.w * sc;
        }
    }

    float m[4], l[4], o[4][4];
#pragma unroll
    for (int i = 0; i < 4; i++) {
        m[i] = -1e30f; l[i] = 0.f;
#pragma unroll
        for (int j = 0; j < 4; j++) o[i][j] = 0.f;
    }

    for (int t = 0; t < Sc / KT; t++) {
        const int k0 = t * KT;
        // Load K tile transposed (4x4 register transpose), V tile natural copy
        {
            const int r0 = (tid >> 4) * 4;
            const int dc = (tid & 15) * 4;
#pragma unroll
            for (int r = 0; r < 4; r++) {
                float4 v4 = *(const float4*)&K[base + (size_t)(k0 + r0 + r) * DKc + dc];
                Ks[(dc + 0) * PITCH + r0 + r] = v4.x;
                Ks[(dc + 1) * PITCH + r0 + r] = v4.y;
                Ks[(dc + 2) * PITCH + r0 + r] = v4.z;
                Ks[(dc + 3) * PITCH + r0 + r] = v4.w;
            }
#pragma unroll
            for (int i = 0; i < 4; i++) {
                int idx = tid + i * 256;
                int kr = idx >> 4;
                int d4 = (idx & 15) * 4;
                *(float4*)&Vs[kr * PITCH + d4] =
                    *(const float4*)&V[base + (size_t)(k0 + kr) * DKc + d4];
            }
        }
        __syncthreads();

        // S = Q K^T  (thread tile: rows ty*4+i, cols tx*4+j)
        float s[4][4];
#pragma unroll
        for (int i = 0; i < 4; i++)
#pragma unroll
            for (int j = 0; j < 4; j++) s[i][j] = 0.f;

#pragma unroll 16
        for (int d = 0; d < 64; d++) {
            float4 qv = *(const float4*)&Qs[d * PITCH + ty * 4];
            float4 kv = *(const float4*)&Ks[d * PITCH + tx * 4];
            s[0][0] = fmaf(qv.x, kv.x, s[0][0]); s[0][1] = fmaf(qv.x, kv.y, s[0][1]);
            s[0][2] = fmaf(qv.x, kv.z, s[0][2]); s[0][3] = fmaf(qv.x, kv.w, s[0][3]);
            s[1][0] = fmaf(qv.y, kv.x, s[1][0]); s[1][1] = fmaf(qv.y, kv.y, s[1][1]);
            s[1][2] = fmaf(qv.y, kv.z, s[1][2]); s[1][3] = fmaf(qv.y, kv.w, s[1][3]);
            s[2][0] = fmaf(qv.z, kv.x, s[2][0]); s[2][1] = fmaf(qv.z, kv.y, s[2][1]);
            s[2][2] = fmaf(qv.z, kv.z, s[2][2]); s[2][3] = fmaf(qv.z, kv.w, s[2][3]);
            s[3][0] = fmaf(qv.w, kv.x, s[3][0]); s[3][1] = fmaf(qv.w, kv.y, s[3][1]);
            s[3][2] = fmaf(qv.w, kv.z, s[3][2]); s[3][3] = fmaf(qv.w, kv.w, s[3][3]);
        }

        // Online softmax. Rows 4ty+i reduce across the 16 tx lanes.
        float mt[4], al[4], rs[4];
#pragma unroll
        for (int i = 0; i < 4; i++) {
            mt[i] = fmaxf(fmaxf(s[i][0], s[i][1]), fmaxf(s[i][2], s[i][3]));
        }
#pragma unroll
        for (int off = 8; off > 0; off >>= 1)
#pragma unroll
            for (int i = 0; i < 4; i++)
                mt[i] = fmaxf(mt[i], __shfl_xor_sync(0xffffffffu, mt[i], off));

#pragma unroll
        for (int i = 0; i < 4; i++) {
            float mn = fmaxf(m[i], mt[i]);
            al[i] = __expf(m[i] - mn);
            m[i] = mn;
            s[i][0] = __expf(s[i][0] - mn);
            s[i][1] = __expf(s[i][1] - mn);
            s[i][2] = __expf(s[i][2] - mn);
            s[i][3] = __expf(s[i][3] - mn);
            rs[i] = (s[i][0] + s[i][1]) + (s[i][2] + s[i][3]);
        }
#pragma unroll
        for (int off = 8; off > 0; off >>= 1)
#pragma unroll
            for (int i = 0; i < 4; i++)
                rs[i] += __shfl_xor_sync(0xffffffffu, rs[i], off);

#pragma unroll
        for (int i = 0; i < 4; i++) {
            l[i] = l[i] * al[i] + rs[i];
#pragma unroll
            for (int j = 0; j < 4; j++) o[i][j] *= al[i];
        }

        // Stage P transposed: Ps[k][q]
#pragma unroll
        for (int j = 0; j < 4; j++) {
            float4 pv = make_float4(s[0][j], s[1][j], s[2][j], s[3][j]);
            *(float4*)&Ps[(tx * 4 + j) * PITCH + ty * 4] = pv;
        }
        __syncthreads();

        // O += P @ V   (thread tile: rows ty*4+i, d-cols tx*4+j)
#pragma unroll 16
        for (int k = 0; k < 64; k++) {
            float4 pv = *(const float4*)&Ps[k * PITCH + ty * 4];
            float4 vv = *(const float4*)&Vs[k * PITCH + tx * 4];
            o[0][0] = fmaf(pv.x, vv.x, o[0][0]); o[0][1] = fmaf(pv.x, vv.y, o[0][1]);
            o[0][2] = fmaf(pv.x, vv.z, o[0][2]); o[0][3] = fmaf(pv.x, vv.w, o[0][3]);
            o[1][0] = fmaf(pv.y, vv.x, o[1][0]); o[1][1] = fmaf(pv.y, vv.y, o[1][1]);
            o[1][2] = fmaf(pv.y, vv.z, o[1][2]); o[1][3] = fmaf(pv.y, vv.w, o[1][3]);
            o[2][0] = fmaf(pv.z, vv.x, o[2][0]); o[2][1] = fmaf(pv.z, vv.y, o[2][1]);
            o[2][2] = fmaf(pv.z, vv.z, o[2][2]); o[2][3] = fmaf(pv.z, vv.w, o[2][3]);
            o[3][0] = fmaf(pv.w, vv.x, o[3][0]); o[3][1] = fmaf(pv.w, vv.y, o[3][1]);
            o[3][2] = fmaf(pv.w, vv.z, o[3][2]); o[3][3] = fmaf(pv.w, vv.w, o[3][3]);
        }
        __syncthreads();
    }

    // Normalize and store
#pragma unroll
    for (int i = 0; i < 4; i++) {
        float inv = 1.f / l[i];
        float4 ov = make_float4(o[i][0] * inv, o[i][1] * inv,
                                o[i][2] * inv, o[i][3] * inv);
        *(float4*)&O[base + (size_t)(q0 + ty * 4 + i) * DKc + tx * 4] = ov;
    }
}

// ---------------------------------------------------------------------------
// Fused residual add + LayerNorm. One block per row of 1024.
// ---------------------------------------------------------------------------
__global__ __launch_bounds__(256) void add_ln(
    const float* __restrict__ resid, const float* __restrict__ xo,
    const float* __restrict__ gamma, const float* __restrict__ beta,
    float* __restrict__ out)
{
    const int row = blockIdx.x;
    const int tid = threadIdx.x;
    const size_t off = (size_t)row * Dc + tid * 4;

    float4 r4 = *(const float4*)&resid[off];
    float4 x4 = *(const float4*)&xo[off];
    float v0 = r4.x + x4.x, v1 = r4.y + x4.y, v2 = r4.z + x4.z, v3 = r4.w + x4.w;

    float sum = (v0 + v1) + (v2 + v3);
    float sq  = (v0 * v0 + v1 * v1) + (v2 * v2 + v3 * v3);

#pragma unroll
    for (int o2 = 16; o2 > 0; o2 >>= 1) {
        sum += __shfl_xor_sync(0xffffffffu, sum, o2);
        sq  += __shfl_xor_sync(0xffffffffu, sq,  o2);
    }

    __shared__ float ssum[8], ssq[8];
    __shared__ float s_mean, s_rstd;
    const int lane = tid & 31, w = tid >> 5;
    if (lane == 0) { ssum[w] = sum; ssq[w] = sq; }
    __syncthreads();
    if (tid == 0) {
        float ts = 0.f, tq = 0.f;
#pragma unroll
        for (int i = 0; i < 8; i++) { ts += ssum[i]; tq += ssq[i]; }
        float mean = ts * (1.f / Dc);
        float var  = tq * (1.f / Dc) - mean * mean;
        s_mean = mean;
        s_rstd = rsqrtf(var + 1e-6f);
    }
    __syncthreads();
    const float mean = s_mean, rstd = s_rstd;

    float4 g4 = *(const float4*)&gamma[tid * 4];
    float4 b4 = *(const float4*)&beta[tid * 4];
    float4 y;
    y.x = (v0 - mean) * rstd * g4.x + b4.x;
    y.y = (v1 - mean) * rstd * g4.y + b4.y;
    y.z = (v2 - mean) * rstd * g4.z + b4.z;
    y.w = (v3 - mean) * rstd * g4.w + b4.w;
    *(float4*)&out[off] = y;
}

// ---------------------------------------------------------------------------
extern "C" void kernel_launch(void* const* d_in, const int* in_sizes, int n_in,
                              void* d_out, int out_size)
{
    const float* q     = (const float*)d_in[0];
    const float* k     = (const float*)d_in[1];
    const float* v     = (const float*)d_in[2];
    const float* Wq    = (const float*)d_in[3];
    const float* bq    = (const float*)d_in[4];
    const float* Wk    = (const float*)d_in[5];
    const float* bk    = (const float*)d_in[6];
    const float* Wv    = (const float*)d_in[7];
    const float* bv    = (const float*)d_in[8];
    const float* Wo    = (const float*)d_in[9];
    const float* bo    = (const float*)d_in[10];
    const float* gamma = (const float*)d_in[11];
    const float* beta  = (const float*)d_in[12];
    float* out = (float*)d_out;

    // Stateless every call: no static guards (harness rule). These are
    // host-side, non-stream API calls — legal under graph capture.
    float *p_QP, *p_KP, *p_VP, *p_CTX, *p_XO;
    cudaGetSymbolAddress((void**)&p_QP,  g_QP);
    cudaGetSymbolAddress((void**)&p_KP,  g_KP);
    cudaGetSymbolAddress((void**)&p_VP,  g_VP);
    cudaGetSymbolAddress((void**)&p_CTX, g_CTX);
    cudaGetSymbolAddress((void**)&p_XO,  g_XO);
    cudaFuncSetAttribute(flash_attn,
                         cudaFuncAttributeMaxDynamicSharedMemorySize,
                         (int)FLASH_SMEM);

    const dim3 gemm_grid(Dc / 128, MROWS / 128);   // (8, 64)

    gemm_nt_bias<<<gemm_grid, 256>>>(q, Wq, bq, p_QP, MROWS, Dc, Dc);
    gemm_nt_bias<<<gemm_grid, 256>>>(k, Wk, bk, p_KP, MROWS, Dc, Dc);
    gemm_nt_bias<<<gemm_grid, 256>>>(v, Wv, bv, p_VP, MROWS, Dc, Dc);

    flash_attn<<<dim3(Sc / QT, GROUPS), 256, FLASH_SMEM>>>(p_QP, p_KP, p_VP, p_CTX);

    gemm_nt_bias<<<gemm_grid, 256>>>(p_CTX, Wo, bo, p_XO, MROWS, Dc, Dc);

    add_ln<<<MROWS, 256>>>(q, p_XO, gamma, beta, out);
}

// round 4
// speedup vs baseline: 2.9565x; 2.9565x over previous
#include <cuda_runtime.h>
#include <math.h>
#include <stdint.h>

// Problem constants
constexpr int Bc  = 4;
constexpr int Sc  = 2048;
constexpr int Dc  = 1024;
constexpr int DKc = 64;
constexpr int MROWS  = Bc * Sc;          // 8192
constexpr int GROUPS = Bc * (Dc / DKc);  // 64

// Scratch (device globals: no allocation allowed)
__device__ float g_QP[MROWS * Dc];
__device__ float g_KP[MROWS * Dc];
__device__ float g_VP[MROWS * Dc];
__device__ float g_CTX[MROWS * Dc];
__device__ float g_XO[MROWS * Dc];

// ---------------------------------------------------------------------------
// tf32 helpers
// ---------------------------------------------------------------------------
__device__ __forceinline__ uint32_t f2tf32(float x) {
    uint32_t r;
    asm("cvt.rna.tf32.f32 %0, %1;" : "=r"(r) : "f"(x));
    return r;
}

__device__ __forceinline__ void mma_tf32(float c[4],
    uint32_t a0, uint32_t a1, uint32_t a2, uint32_t a3,
    uint32_t b0, uint32_t b1)
{
    asm volatile(
        "mma.sync.aligned.m16n8k8.row.col.f32.tf32.tf32.f32 "
        "{%0,%1,%2,%3}, {%4,%5,%6,%7}, {%8,%9}, {%0,%1,%2,%3};\n"
        : "+f"(c[0]), "+f"(c[1]), "+f"(c[2]), "+f"(c[3])
        : "r"(a0), "r"(a1), "r"(a2), "r"(a3), "r"(b0), "r"(b1));
}

// ---------------------------------------------------------------------------
// tf32 NT GEMM computing Ct = W * A^T per tile, stored as C[m,n] = A@W^T + b.
//   A [M,K] row-major (activations), W [N,K] row-major (weights).
// Block tile: 128 n x 128 m, BK=32. 8 warps: 2 (n) x 4 (m).
// smem pitch 36 (== 4 mod 32) -> conflict-free fragment loads.
// ---------------------------------------------------------------------------
constexpr int GP = 36;

__global__ __launch_bounds__(256, 2) void gemm_tf32_nt(
    const float* __restrict__ A, const float* __restrict__ W,
    const float* __restrict__ bias, float* __restrict__ C,
    int M, int N, int K)
{
    __shared__ uint32_t Ws_s[128 * GP];   // [n][k]
    __shared__ uint32_t As_s[128 * GP];   // [m][k]

    const int bm = blockIdx.x * 128;      // activation rows
    const int bn = blockIdx.y * 128;      // weight rows (output cols)
    const int tid  = threadIdx.x;
    const int wid  = tid >> 5;
    const int lane = tid & 31;
    const int gq   = lane >> 2;           // group id (0..7)
    const int tig  = lane & 3;            // thread in group
    const int wn = (wid & 1) * 64;        // warp n offset
    const int wm = (wid >> 1) * 32;       // warp m offset

    float acc[4][4][4];
#pragma unroll
    for (int ni = 0; ni < 4; ni++)
#pragma unroll
        for (int mi = 0; mi < 4; mi++)
#pragma unroll
            for (int r = 0; r < 4; r++) acc[ni][mi][r] = 0.f;

    const int kq = (tid & 7) * 4;         // k float4 offset
    const int r0 = tid >> 3;              // row 0..31

    for (int k0 = 0; k0 < K; k0 += 32) {
#pragma unroll
        for (int it = 0; it < 4; it++) {
            int r = r0 + it * 32;
            float4 av = *(const float4*)&A[(size_t)(bm + r) * K + k0 + kq];
            uint4 au = make_uint4(f2tf32(av.x), f2tf32(av.y), f2tf32(av.z), f2tf32(av.w));
            *(uint4*)&As_s[r * GP + kq] = au;
            float4 wv = *(const float4*)&W[(size_t)(bn + r) * K + k0 + kq];
            uint4 wu = make_uint4(f2tf32(wv.x), f2tf32(wv.y), f2tf32(wv.z), f2tf32(wv.w));
            *(uint4*)&Ws_s[r * GP + kq] = wu;
        }
        __syncthreads();

#pragma unroll
        for (int k8 = 0; k8 < 4; k8++) {
            const int kk = k8 * 8;
            uint32_t aW[4][4], bA[4][2];
#pragma unroll
            for (int ni = 0; ni < 4; ni++) {
                int nb = wn + ni * 16;
                aW[ni][0] = Ws_s[(nb + gq) * GP + kk + tig];
                aW[ni][1] = Ws_s[(nb + 8 + gq) * GP + kk + tig];
                aW[ni][2] = Ws_s[(nb + gq) * GP + kk + 4 + tig];
                aW[ni][3] = Ws_s[(nb + 8 + gq) * GP + kk + 4 + tig];
            }
#pragma unroll
            for (int mi = 0; mi < 4; mi++) {
                int mb = wm + mi * 8;
                bA[mi][0] = As_s[(mb + gq) * GP + kk + tig];
                bA[mi][1] = As_s[(mb + gq) * GP + kk + 4 + tig];
            }
#pragma unroll
            for (int ni = 0; ni < 4; ni++)
#pragma unroll
                for (int mi = 0; mi < 4; mi++)
                    mma_tf32(acc[ni][mi], aW[ni][0], aW[ni][1], aW[ni][2], aW[ni][3],
                             bA[mi][0], bA[mi][1]);
        }
        __syncthreads();
    }

    // Epilogue: C[m,n] = acc + bias[n]
#pragma unroll
    for (int ni = 0; ni < 4; ni++) {
        int n_lo = bn + wn + ni * 16 + gq;
        int n_hi = n_lo + 8;
        float blo = bias[n_lo];
        float bhi = bias[n_hi];
#pragma unroll
        for (int mi = 0; mi < 4; mi++) {
            int mc = bm + wm + mi * 8 + 2 * tig;
            C[(size_t)mc * N + n_lo]       = acc[ni][mi][0] + blo;
            C[(size_t)(mc + 1) * N + n_lo] = acc[ni][mi][1] + blo;
            C[(size_t)mc * N + n_hi]       = acc[ni][mi][2] + bhi;
            C[(size_t)(mc + 1) * N + n_hi] = acc[ni][mi][3] + bhi;
        }
    }
}

// ---------------------------------------------------------------------------
// tf32 flash attention over [GROUPS, Sc, DKc] contiguous views.
// Block: 128 q rows x full DK=64. 8 warps, 16 q rows each.
// Q fragments preloaded to registers (direct GMEM, held across KV loop).
// K tile natural copy to smem; V transposed into smem; P repacked via shfl.
// smem pitch 68 (== 4 mod 32) -> conflict-free fragment loads.
// ---------------------------------------------------------------------------
constexpr int FP = 68;

__global__ __launch_bounds__(256, 2) void flash_tf32(
    const float* __restrict__ Q, const float* __restrict__ K,
    const float* __restrict__ V, float* __restrict__ O)
{
    __shared__ uint32_t Ks_s[64 * FP];   // [kn][dk]
    __shared__ uint32_t Vt_s[64 * FP];   // [d][kn]

    const int grp = blockIdx.y;
    const int q0  = blockIdx.x * 128;
    const size_t base = (size_t)grp * Sc * DKc;
    const int tid  = threadIdx.x;
    const int wid  = tid >> 5;
    const int lane = tid & 31;
    const int gq   = lane >> 2;
    const int tig  = lane & 3;
    const int qw   = q0 + wid * 16;      // warp's q base

    // Preload Q fragments (scaled by 1/sqrt(64)), held for all 32 KV tiles.
    uint32_t aQ[8][4];
#pragma unroll
    for (int k8 = 0; k8 < 8; k8++) {
        const int kk = k8 * 8;
        aQ[k8][0] = f2tf32(0.125f * Q[base + (size_t)(qw + gq) * 64 + kk + tig]);
        aQ[k8][1] = f2tf32(0.125f * Q[base + (size_t)(qw + 8 + gq) * 64 + kk + tig]);
        aQ[k8][2] = f2tf32(0.125f * Q[base + (size_t)(qw + gq) * 64 + kk + 4 + tig]);
        aQ[k8][3] = f2tf32(0.125f * Q[base + (size_t)(qw + 8 + gq) * 64 + kk + 4 + tig]);
    }

    float o[8][4];
#pragma unroll
    for (int dt = 0; dt < 8; dt++)
#pragma unroll
        for (int r = 0; r < 4; r++) o[dt][r] = 0.f;
    float m0 = -1e30f, m1 = -1e30f, l0 = 0.f, l1 = 0.f;

    const int kr  = tid >> 4;            // K-load: row 0..15 (+16*it)
    const int f4  = (tid & 15) * 4;      // K-load: float col
    const int vkn = tid >> 2;            // V-load: kn row 0..63
    const int vdq = (tid & 3) * 16;      // V-load: d base

    for (int t = 0; t < Sc / 64; t++) {
        const int k0 = t * 64;
        // K tile: natural copy [kn][dk]
#pragma unroll
        for (int it = 0; it < 4; it++) {
            int r = kr + it * 16;
            float4 kv = *(const float4*)&K[base + (size_t)(k0 + r) * 64 + f4];
            uint4 ku = make_uint4(f2tf32(kv.x), f2tf32(kv.y), f2tf32(kv.z), f2tf32(kv.w));
            *(uint4*)&Ks_s[r * FP + f4] = ku;
        }
        // V tile: transposed scatter [d][kn]
#pragma unroll
        for (int i2 = 0; i2 < 4; i2++) {
            int d = vdq + i2 * 4;
            float4 vv = *(const float4*)&V[base + (size_t)(k0 + vkn) * 64 + d];
            Vt_s[(d + 0) * FP + vkn] = f2tf32(vv.x);
            Vt_s[(d + 1) * FP + vkn] = f2tf32(vv.y);
            Vt_s[(d + 2) * FP + vkn] = f2tf32(vv.z);
            Vt_s[(d + 3) * FP + vkn] = f2tf32(vv.w);
        }
        __syncthreads();

        // S = Q K^T for this warp's 16 q rows x 64 kn
        float s[8][4];
#pragma unroll
        for (int nt = 0; nt < 8; nt++) {
#pragma unroll
            for (int r = 0; r < 4; r++) s[nt][r] = 0.f;
#pragma unroll
            for (int k8 = 0; k8 < 8; k8++) {
                const int kk = k8 * 8;
                uint32_t b0 = Ks_s[(nt * 8 + gq) * FP + kk + tig];
                uint32_t b1 = Ks_s[(nt * 8 + gq) * FP + kk + 4 + tig];
                mma_tf32(s[nt], aQ[k8][0], aQ[k8][1], aQ[k8][2], aQ[k8][3], b0, b1);
            }
        }

        // Online softmax. Row of thread: q = gq (regs 0,1) and gq+8 (regs 2,3),
        // spread over the 4 lanes of the quad.
        float mx0 = -1e30f, mx1 = -1e30f;
#pragma unroll
        for (int nt = 0; nt < 8; nt++) {
            mx0 = fmaxf(mx0, fmaxf(s[nt][0], s[nt][1]));
            mx1 = fmaxf(mx1, fmaxf(s[nt][2], s[nt][3]));
        }
        mx0 = fmaxf(mx0, __shfl_xor_sync(0xffffffffu, mx0, 1));
        mx0 = fmaxf(mx0, __shfl_xor_sync(0xffffffffu, mx0, 2));
        mx1 = fmaxf(mx1, __shfl_xor_sync(0xffffffffu, mx1, 1));
        mx1 = fmaxf(mx1, __shfl_xor_sync(0xffffffffu, mx1, 2));

        float nm0 = fmaxf(m0, mx0), nm1 = fmaxf(m1, mx1);
        float al0 = __expf(m0 - nm0), al1 = __expf(m1 - nm1);
        m0 = nm0; m1 = nm1;

        float rs0 = 0.f, rs1 = 0.f;
#pragma unroll
        for (int nt = 0; nt < 8; nt++) {
            s[nt][0] = __expf(s[nt][0] - nm0);
            s[nt][1] = __expf(s[nt][1] - nm0);
            s[nt][2] = __expf(s[nt][2] - nm1);
            s[nt][3] = __expf(s[nt][3] - nm1);
            rs0 += s[nt][0] + s[nt][1];
            rs1 += s[nt][2] + s[nt][3];
        }
        rs0 += __shfl_xor_sync(0xffffffffu, rs0, 1);
        rs0 += __shfl_xor_sync(0xffffffffu, rs0, 2);
        rs1 += __shfl_xor_sync(0xffffffffu, rs1, 1);
        rs1 += __shfl_xor_sync(0xffffffffu, rs1, 2);
        l0 = l0 * al0 + rs0;
        l1 = l1 * al1 + rs1;

#pragma unroll
        for (int dt = 0; dt < 8; dt++) {
            o[dt][0] *= al0; o[dt][1] *= al0;
            o[dt][2] *= al1; o[dt][3] *= al1;
        }

        // PV: repack P C-frag -> A-frag via quad shuffles, then mma into o.
        const int srcl = (lane & ~3) | (tig >> 1);
#pragma unroll
        for (int nt = 0; nt < 8; nt++) {
            float u0 = __shfl_sync(0xffffffffu, s[nt][0], srcl);
            float u1 = __shfl_sync(0xffffffffu, s[nt][1], srcl);
            float w0 = __shfl_sync(0xffffffffu, s[nt][0], srcl + 2);
            float w1 = __shfl_sync(0xffffffffu, s[nt][1], srcl + 2);
            float x0 = __shfl_sync(0xffffffffu, s[nt][2], srcl);
            float x1 = __shfl_sync(0xffffffffu, s[nt][3], srcl);
            float y0 = __shfl_sync(0xffffffffu, s[nt][2], srcl + 2);
            float y1 = __shfl_sync(0xffffffffu, s[nt][3], srcl + 2);
            uint32_t a0 = f2tf32((tig & 1) ? u1 : u0);
            uint32_t a2 = f2tf32((tig & 1) ? w1 : w0);
            uint32_t a1 = f2tf32((tig & 1) ? x1 : x0);
            uint32_t a3 = f2tf32((tig & 1) ? y1 : y0);
#pragma unroll
            for (int dt = 0; dt < 8; dt++) {
                uint32_t b0 = Vt_s[(dt * 8 + gq) * FP + nt * 8 + tig];
                uint32_t b1 = Vt_s[(dt * 8 + gq) * FP + nt * 8 + 4 + tig];
                mma_tf32(o[dt], a0, a1, a2, a3, b0, b1);
            }
        }
        __syncthreads();
    }

    // Normalize and store (float2 per fragment row pair)
    const float inv0 = 1.f / l0, inv1 = 1.f / l1;
#pragma unroll
    for (int dt = 0; dt < 8; dt++) {
        float2 lo = make_float2(o[dt][0] * inv0, o[dt][1] * inv0);
        float2 hi = make_float2(o[dt][2] * inv1, o[dt][3] * inv1);
        *(float2*)&O[base + (size_t)(qw + gq) * 64 + dt * 8 + 2 * tig]     = lo;
        *(float2*)&O[base + (size_t)(qw + 8 + gq) * 64 + dt * 8 + 2 * tig] = hi;
    }
}

// ---------------------------------------------------------------------------
// Fused residual add + LayerNorm. One block per row of 1024.
// ---------------------------------------------------------------------------
__global__ __launch_bounds__(256) void add_ln(
    const float* __restrict__ resid, const float* __restrict__ xo,
    const float* __restrict__ gamma, const float* __restrict__ beta,
    float* __restrict__ out)
{
    const int row = blockIdx.x;
    const int tid = threadIdx.x;
    const size_t off = (size_t)row * Dc + tid * 4;

    float4 r4 = *(const float4*)&resid[off];
    float4 x4 = *(const float4*)&xo[off];
    float v0 = r4.x + x4.x, v1 = r4.y + x4.y, v2 = r4.z + x4.z, v3 = r4.w + x4.w;

    float sum = (v0 + v1) + (v2 + v3);
    float sq  = (v0 * v0 + v1 * v1) + (v2 * v2 + v3 * v3);

#pragma unroll
    for (int o2 = 16; o2 > 0; o2 >>= 1) {
        sum += __shfl_xor_sync(0xffffffffu, sum, o2);
        sq  += __shfl_xor_sync(0xffffffffu, sq,  o2);
    }

    __shared__ float ssum[8], ssq[8];
    __shared__ float s_mean, s_rstd;
    const int lane = tid & 31, w = tid >> 5;
    if (lane == 0) { ssum[w] = sum; ssq[w] = sq; }
    __syncthreads();
    if (tid == 0) {
        float ts = 0.f, tq = 0.f;
#pragma unroll
        for (int i = 0; i < 8; i++) { ts += ssum[i]; tq += ssq[i]; }
        float mean = ts * (1.f / Dc);
        float var  = tq * (1.f / Dc) - mean * mean;
        s_mean = mean;
        s_rstd = rsqrtf(var + 1e-6f);
    }
    __syncthreads();
    const float mean = s_mean, rstd = s_rstd;

    float4 g4 = *(const float4*)&gamma[tid * 4];
    float4 b4 = *(const float4*)&beta[tid * 4];
    float4 y;
    y.x = (v0 - mean) * rstd * g4.x + b4.x;
    y.y = (v1 - mean) * rstd * g4.y + b4.y;
    y.z = (v2 - mean) * rstd * g4.z + b4.z;
    y.w = (v3 - mean) * rstd * g4.w + b4.w;
    *(float4*)&out[off] = y;
}

// ---------------------------------------------------------------------------
extern "C" void kernel_launch(void* const* d_in, const int* in_sizes, int n_in,
                              void* d_out, int out_size)
{
    const float* q     = (const float*)d_in[0];
    const float* k     = (const float*)d_in[1];
    const float* v     = (const float*)d_in[2];
    const float* Wq    = (const float*)d_in[3];
    const float* bq    = (const float*)d_in[4];
    const float* Wk    = (const float*)d_in[5];
    const float* bk    = (const float*)d_in[6];
    const float* Wv    = (const float*)d_in[7];
    const float* bv    = (const float*)d_in[8];
    const float* Wo    = (const float*)d_in[9];
    const float* bo    = (const float*)d_in[10];
    const float* gamma = (const float*)d_in[11];
    const float* beta  = (const float*)d_in[12];
    float* out = (float*)d_out;

    float *p_QP, *p_KP, *p_VP, *p_CTX, *p_XO;
    cudaGetSymbolAddress((void**)&p_QP,  g_QP);
    cudaGetSymbolAddress((void**)&p_KP,  g_KP);
    cudaGetSymbolAddress((void**)&p_VP,  g_VP);
    cudaGetSymbolAddress((void**)&p_CTX, g_CTX);
    cudaGetSymbolAddress((void**)&p_XO,  g_XO);

    const dim3 gemm_grid(MROWS / 128, Dc / 128);   // (64, 8)

    gemm_tf32_nt<<<gemm_grid, 256>>>(q, Wq, bq, p_QP, MROWS, Dc, Dc);
    gemm_tf32_nt<<<gemm_grid, 256>>>(k, Wk, bk, p_KP, MROWS, Dc, Dc);
    gemm_tf32_nt<<<gemm_grid, 256>>>(v, Wv, bv, p_VP, MROWS, Dc, Dc);

    flash_tf32<<<dim3(Sc / 128, GROUPS), 256>>>(p_QP, p_KP, p_VP, p_CTX);

    gemm_tf32_nt<<<gemm_grid, 256>>>(p_CTX, Wo, bo, p_XO, MROWS, Dc, Dc);

    add_ln<<<MROWS, 256>>>(q, p_XO, gamma, beta, out);
}